// round 1
// baseline (speedup 1.0000x reference)
#include <cuda_runtime.h>
#include <math.h>
#include <stdint.h>

#define VOCAB 50000
#define EMB   512
#define HID   1024
#define G4    4096   // 4*HID
#define TT    256
#define BB    256

// ---------------- device scratch (no allocations allowed) ----------------
__device__ float g_xg[(size_t)TT * BB * G4];   // [T][B][4H] precomputed input gates (+biases)
__device__ float g_gates[(size_t)BB * G4];     // per-step gate scratch [B][4H]
__device__ float g_h[BB * HID];
__device__ float g_c[BB * HID];
__device__ int   g_is64;

// ---------------- dtype probe: is `text` int64 or int32? ----------------
// If the buffer is int32, interpreting it as int64 combines two tokens ->
// values >= 2^32 almost surely (token range [0,50000)). Check 64 entries.
__global__ void detect_dtype(const void* text) {
    if (threadIdx.x == 0 && blockIdx.x == 0) {
        const long long* p = (const long long*)text;
        int ok = 1;
        for (int i = 0; i < 64; i++) {
            long long v = p[i];
            if (v < 0 || v >= VOCAB) ok = 0;
        }
        g_is64 = ok;
    }
}

__global__ void zero_hc() {
    int i = blockIdx.x * blockDim.x + threadIdx.x;
    if (i < BB * HID) { g_h[i] = 0.f; g_c[i] = 0.f; }
}

// ---------------- fused embedding gather + input GEMM ----------------
// xg[t][b][g] = sum_e emb[text[b][t]][e] * w_ih[g][e] + b_ih[g] + b_hh[g]
// M = 65536 tokens (m = b*T + t), N = 4096 gates, K = 512.
// 128x128 tile, BK=16, 256 threads, 8x8 micro-tile (split 4+4 for float4 LDS).
__global__ __launch_bounds__(256) void embed_gemm(
    const void* __restrict__ text,
    const float* __restrict__ emb,
    const float* __restrict__ w_ih,
    const float* __restrict__ b_ih,
    const float* __restrict__ b_hh)
{
    __shared__ __align__(16) float As[16][128];
    __shared__ __align__(16) float Bs[16][128];
    __shared__ int toks[128];

    const int tid = threadIdx.x;
    const int m0 = blockIdx.x * 128;   // token tile
    const int n0 = blockIdx.y * 128;   // gate tile

    if (tid < 128) {
        int m = m0 + tid;
        toks[tid] = g_is64 ? (int)((const long long*)text)[m]
                           : ((const int*)text)[m];
    }
    __syncthreads();

    const int tx = tid & 15;
    const int ty = tid >> 4;

    float acc[8][8];
#pragma unroll
    for (int i = 0; i < 8; i++)
#pragma unroll
        for (int j = 0; j < 8; j++) acc[i][j] = 0.f;

    for (int k0 = 0; k0 < EMB; k0 += 16) {
        // Load A tile (gathered emb rows) and B tile (w_ih rows):
        // 128 rows x 4 float4 chunks = 512 float4 each; 2 per thread.
#pragma unroll
        for (int l = 0; l < 2; l++) {
            int i  = tid + l * 256;
            int m  = i >> 2;
            int kq = (i & 3) << 2;
            float4 va = *(const float4*)(emb + (size_t)toks[m] * EMB + k0 + kq);
            As[kq + 0][m] = va.x; As[kq + 1][m] = va.y;
            As[kq + 2][m] = va.z; As[kq + 3][m] = va.w;
            float4 vb = *(const float4*)(w_ih + (size_t)(n0 + m) * EMB + k0 + kq);
            Bs[kq + 0][m] = vb.x; Bs[kq + 1][m] = vb.y;
            Bs[kq + 2][m] = vb.z; Bs[kq + 3][m] = vb.w;
        }
        __syncthreads();

#pragma unroll
        for (int k = 0; k < 16; k++) {
            float4 a0 = *(const float4*)&As[k][ty * 4];
            float4 a1 = *(const float4*)&As[k][64 + ty * 4];
            float4 b0 = *(const float4*)&Bs[k][tx * 4];
            float4 b1 = *(const float4*)&Bs[k][64 + tx * 4];
            float a[8] = {a0.x, a0.y, a0.z, a0.w, a1.x, a1.y, a1.z, a1.w};
            float b[8] = {b0.x, b0.y, b0.z, b0.w, b1.x, b1.y, b1.z, b1.w};
#pragma unroll
            for (int i = 0; i < 8; i++)
#pragma unroll
                for (int j = 0; j < 8; j++) acc[i][j] += a[i] * b[j];
        }
        __syncthreads();
    }

    // Epilogue: scatter to [T][B][4H] layout, add biases.
#pragma unroll
    for (int i = 0; i < 8; i++) {
        int row = (i < 4) ? (ty * 4 + i) : (64 + ty * 4 + (i - 4));
        int m = m0 + row;
        int bb = m >> 8;      // batch
        int t  = m & 255;     // time
        size_t base = ((size_t)t * BB + bb) * G4 + n0;
#pragma unroll
        for (int j = 0; j < 8; j++) {
            int col = (j < 4) ? (tx * 4 + j) : (64 + tx * 4 + (j - 4));
            g_xg[base + col] = acc[i][j] + b_ih[n0 + col] + b_hh[n0 + col];
        }
    }
}

// ---------------- per-step recurrent GEMM ----------------
// gates[b][g] = xg[t][b][g] + sum_k h[b][k] * w_hh[g][k]
// M=256 (batch), N=4096, K=1024. 64x64 tile, BK=16, 256 threads, 4x4 micro.
__global__ __launch_bounds__(256) void step_gemm(
    const float* __restrict__ w_hh, int t)
{
    __shared__ __align__(16) float As[16][64];
    __shared__ __align__(16) float Bs[16][64];

    const int tid = threadIdx.x;
    const int m0 = blockIdx.x * 64;   // batch tile (grid.x = 4)
    const int n0 = blockIdx.y * 64;   // gate tile  (grid.y = 64)
    const int tx = tid & 15;
    const int ty = tid >> 4;

    float acc[4][4];
#pragma unroll
    for (int i = 0; i < 4; i++)
#pragma unroll
        for (int j = 0; j < 4; j++) acc[i][j] = 0.f;

    const int lm = tid >> 2;          // 0..63 row
    const int lk = (tid & 3) << 2;    // 0,4,8,12

    for (int k0 = 0; k0 < HID; k0 += 16) {
        float4 va = *(const float4*)(g_h + (size_t)(m0 + lm) * HID + k0 + lk);
        As[lk + 0][lm] = va.x; As[lk + 1][lm] = va.y;
        As[lk + 2][lm] = va.z; As[lk + 3][lm] = va.w;
        float4 vb = *(const float4*)(w_hh + (size_t)(n0 + lm) * HID + k0 + lk);
        Bs[lk + 0][lm] = vb.x; Bs[lk + 1][lm] = vb.y;
        Bs[lk + 2][lm] = vb.z; Bs[lk + 3][lm] = vb.w;
        __syncthreads();

#pragma unroll
        for (int k = 0; k < 16; k++) {
            float4 a = *(const float4*)&As[k][ty * 4];
            float4 b = *(const float4*)&Bs[k][tx * 4];
            float av[4] = {a.x, a.y, a.z, a.w};
            float bv[4] = {b.x, b.y, b.z, b.w};
#pragma unroll
            for (int i = 0; i < 4; i++)
#pragma unroll
                for (int j = 0; j < 4; j++) acc[i][j] += av[i] * bv[j];
        }
        __syncthreads();
    }

#pragma unroll
    for (int i = 0; i < 4; i++) {
        int bb = m0 + ty * 4 + i;
        size_t xbase = ((size_t)t * BB + bb) * G4;
#pragma unroll
        for (int j = 0; j < 4; j++) {
            int g = n0 + tx * 4 + j;
            g_gates[(size_t)bb * G4 + g] = acc[i][j] + g_xg[xbase + g];
        }
    }
}

// ---------------- elementwise LSTM cell update ----------------
__device__ __forceinline__ float sigmoidf_(float x) {
    return 1.f / (1.f + expf(-x));
}

__global__ void step_elem() {
    int idx = blockIdx.x * blockDim.x + threadIdx.x;
    if (idx >= BB * HID) return;
    int bb = idx >> 10;
    int j  = idx & 1023;
    const float* gr = g_gates + (size_t)bb * G4;
    float ig = gr[j];
    float fg = gr[1024 + j];
    float gg = gr[2048 + j];
    float og = gr[3072 + j];
    float c = sigmoidf_(fg) * g_c[idx] + sigmoidf_(ig) * tanhf(gg);
    g_c[idx] = c;
    g_h[idx] = sigmoidf_(og) * tanhf(c);
}

// ---------------- final FC + sigmoid (OUT = 1) ----------------
__global__ void final_fc(const float* __restrict__ fc_w,
                         const float* __restrict__ fc_b,
                         float* __restrict__ out)
{
    int bb = blockIdx.x;
    int tid = threadIdx.x;   // 128 threads
    float s = 0.f;
    for (int k = tid; k < HID; k += 128)
        s += g_h[bb * HID + k] * fc_w[k];
    __shared__ float red[128];
    red[tid] = s;
    __syncthreads();
    for (int off = 64; off > 0; off >>= 1) {
        if (tid < off) red[tid] += red[tid + off];
        __syncthreads();
    }
    if (tid == 0)
        out[bb] = 1.f / (1.f + expf(-(red[0] + fc_b[0])));
}

// ---------------- launch ----------------
extern "C" void kernel_launch(void* const* d_in, const int* in_sizes, int n_in,
                              void* d_out, int out_size)
{
    const void*  text = d_in[0];
    const float* emb  = (const float*)d_in[1];
    const float* w_ih = (const float*)d_in[2];
    const float* w_hh = (const float*)d_in[3];
    const float* b_ih = (const float*)d_in[4];
    const float* b_hh = (const float*)d_in[5];
    const float* fc_w = (const float*)d_in[6];
    const float* fc_b = (const float*)d_in[7];
    float* out = (float*)d_out;

    detect_dtype<<<1, 32>>>(text);
    zero_hc<<<(BB * HID + 255) / 256, 256>>>();

    dim3 g1(512, 32);   // 65536/128 token tiles x 4096/128 gate tiles
    embed_gemm<<<g1, 256>>>(text, emb, w_ih, b_ih, b_hh);

    dim3 g2(4, 64);     // 256/64 batch tiles x 4096/64 gate tiles
    for (int t = 0; t < TT; t++) {
        step_gemm<<<g2, 256>>>(w_hh, t);
        step_elem<<<(BB * HID + 255) / 256, 256>>>();
    }

    final_fc<<<BB, 128>>>(fc_w, fc_b, out);
}

// round 3
// speedup vs baseline: 1.6241x; 1.6241x over previous
#include <cuda_runtime.h>
#include <math.h>
#include <stdint.h>

#define VOCAB 50000
#define EMB   512
#define HID   1024
#define G4    4096   // 4*HID
#define TT    256
#define BB    256

// ---------------- device scratch (no allocations allowed) ----------------
__device__ float g_xg[(size_t)TT * BB * G4];   // [T][B][4H] input gates (+biases)
__device__ float g_hbuf[2][BB * HID];          // double-buffered hidden state
__device__ float g_c[BB * HID];
__device__ int   g_is64;

// ---------------- dtype probe: is `text` int64 or int32? ----------------
__global__ void detect_dtype(const void* text) {
    if (threadIdx.x == 0 && blockIdx.x == 0) {
        const long long* p = (const long long*)text;
        int ok = 1;
        for (int i = 0; i < 64; i++) {
            long long v = p[i];
            if (v < 0 || v >= VOCAB) ok = 0;
        }
        g_is64 = ok;
    }
}

__global__ void zero_hc() {
    int i = blockIdx.x * blockDim.x + threadIdx.x;
    if (i < BB * HID) {
        g_hbuf[0][i] = 0.f;
        g_hbuf[1][i] = 0.f;
        g_c[i] = 0.f;
    }
}

// ---------------- fused embedding gather + input GEMM (fp32 SIMT) ----------------
__global__ __launch_bounds__(256) void embed_gemm(
    const void* __restrict__ text,
    const float* __restrict__ emb,
    const float* __restrict__ w_ih,
    const float* __restrict__ b_ih,
    const float* __restrict__ b_hh)
{
    __shared__ __align__(16) float As[16][128];
    __shared__ __align__(16) float Bs[16][128];
    __shared__ int toks[128];

    const int tid = threadIdx.x;
    const int m0 = blockIdx.x * 128;
    const int n0 = blockIdx.y * 128;

    if (tid < 128) {
        int m = m0 + tid;
        toks[tid] = g_is64 ? (int)((const long long*)text)[m]
                           : ((const int*)text)[m];
    }
    __syncthreads();

    const int tx = tid & 15;
    const int ty = tid >> 4;

    float acc[8][8];
#pragma unroll
    for (int i = 0; i < 8; i++)
#pragma unroll
        for (int j = 0; j < 8; j++) acc[i][j] = 0.f;

    for (int k0 = 0; k0 < EMB; k0 += 16) {
#pragma unroll
        for (int l = 0; l < 2; l++) {
            int i  = tid + l * 256;
            int m  = i >> 2;
            int kq = (i & 3) << 2;
            float4 va = *(const float4*)(emb + (size_t)toks[m] * EMB + k0 + kq);
            As[kq + 0][m] = va.x; As[kq + 1][m] = va.y;
            As[kq + 2][m] = va.z; As[kq + 3][m] = va.w;
            float4 vb = *(const float4*)(w_ih + (size_t)(n0 + m) * EMB + k0 + kq);
            Bs[kq + 0][m] = vb.x; Bs[kq + 1][m] = vb.y;
            Bs[kq + 2][m] = vb.z; Bs[kq + 3][m] = vb.w;
        }
        __syncthreads();

#pragma unroll
        for (int k = 0; k < 16; k++) {
            float4 a0 = *(const float4*)&As[k][ty * 4];
            float4 a1 = *(const float4*)&As[k][64 + ty * 4];
            float4 b0 = *(const float4*)&Bs[k][tx * 4];
            float4 b1 = *(const float4*)&Bs[k][64 + tx * 4];
            float a[8] = {a0.x, a0.y, a0.z, a0.w, a1.x, a1.y, a1.z, a1.w};
            float b[8] = {b0.x, b0.y, b0.z, b0.w, b1.x, b1.y, b1.z, b1.w};
#pragma unroll
            for (int i = 0; i < 8; i++)
#pragma unroll
                for (int j = 0; j < 8; j++) acc[i][j] += a[i] * b[j];
        }
        __syncthreads();
    }

#pragma unroll
    for (int i = 0; i < 8; i++) {
        int row = (i < 4) ? (ty * 4 + i) : (64 + ty * 4 + (i - 4));
        int m = m0 + row;
        int bb = m >> 8;
        int t  = m & 255;
        size_t base = ((size_t)t * BB + bb) * G4 + n0;
#pragma unroll
        for (int j = 0; j < 8; j++) {
            int col = (j < 4) ? (tx * 4 + j) : (64 + tx * 4 + (j - 4));
            g_xg[base + col] = acc[i][j] + b_ih[n0 + col] + b_hh[n0 + col];
        }
    }
}

// ---------------- tf32 MMA helpers ----------------
__device__ __forceinline__ uint32_t f2tf32(float f) {
    uint32_t r;
    asm("cvt.rna.tf32.f32 %0, %1;" : "=r"(r) : "f"(f));
    return r;
}

__device__ __forceinline__ void mma_tf32(float4& d,
                                         uint32_t a0, uint32_t a1, uint32_t a2, uint32_t a3,
                                         uint32_t b0, uint32_t b1) {
    asm volatile(
        "mma.sync.aligned.m16n8k8.row.col.f32.tf32.tf32.f32 "
        "{%0,%1,%2,%3}, {%4,%5,%6,%7}, {%8,%9}, {%0,%1,%2,%3};"
        : "+f"(d.x), "+f"(d.y), "+f"(d.z), "+f"(d.w)
        : "r"(a0), "r"(a1), "r"(a2), "r"(a3), "r"(b0), "r"(b1));
}

// ---------------- fused per-step: h@w_hh^T (+xg) + LSTM cell update ----------------
// Block: batch tile BM=64 (blockIdx.x in 0..3), hidden tile BJ=32 (blockIdx.y in 0..31).
// Computes all 4 gates for its (b,j) tile -> 64x128 gate tile -> c/h update fused.
#define BM 64
#define BJ 32
#define BNg 128        // 4 gates * BJ
#define BK 32
#define APAD 36        // (36*n + k) % 32 = (4n + k) % 32 -> conflict-free fragments
#define GPAD 129
// GEMM phase needs BM*APAD + BNg*APAD = 6912 floats.
// Epilogue gate buffer (overlaid) needs BM*GPAD = 8256 floats. Take the max.
#define SMEM_FLOATS 8256

__global__ __launch_bounds__(256) void step_fused(
    const float* __restrict__ w_hh,
    const float* __restrict__ hin,
    float* __restrict__ hout,
    int t)
{
    __shared__ __align__(16) float smem[SMEM_FLOATS];  // 33 KB
    float* As = smem;                  // [BM][APAD]
    float* Bs = smem + BM * APAD;      // [BNg][APAD]
    float* Gs = smem;                  // epilogue overlay: [BM][GPAD]

    const int tid  = threadIdx.x;
    const int lane = tid & 31;
    const int warp = tid >> 5;          // 8 warps: 4 M x 2 N
    const int wm   = warp >> 1;         // 0..3
    const int wn   = warp & 1;          // 0..1
    const int m_off = wm * 16;
    const int n_off = wn * 64;
    const int gid  = lane >> 2;         // group id 0..7
    const int tig  = lane & 3;          // thread in group 0..3

    const int b0 = blockIdx.x * BM;     // batch tile base
    const int j0 = blockIdx.y * BJ;     // hidden tile base

    float4 acc[8];
#pragma unroll
    for (int i = 0; i < 8; i++) acc[i] = make_float4(0.f, 0.f, 0.f, 0.f);

    for (int k0 = 0; k0 < HID; k0 += BK) {
        // Load A tile: 64 x 32 = 512 float4, 2 per thread.
#pragma unroll
        for (int l = 0; l < 2; l++) {
            int idx = tid + l * 256;
            int row = idx >> 3;
            int kq  = (idx & 7) << 2;
            float4 v = *(const float4*)(hin + (size_t)(b0 + row) * HID + k0 + kq);
            float* p = As + row * APAD + kq;
            p[0] = v.x; p[1] = v.y; p[2] = v.z; p[3] = v.w;
        }
        // Load B tile: 128 x 32 = 1024 float4, 4 per thread.
#pragma unroll
        for (int l = 0; l < 4; l++) {
            int idx = tid + l * 256;
            int row = idx >> 3;              // 0..127  (= gate*32 + jj)
            int kq  = (idx & 7) << 2;
            int nglob = (row >> 5) * HID + j0 + (row & 31);
            float4 v = *(const float4*)(w_hh + (size_t)nglob * HID + k0 + kq);
            float* p = Bs + row * APAD + kq;
            p[0] = v.x; p[1] = v.y; p[2] = v.z; p[3] = v.w;
        }
        __syncthreads();

#pragma unroll
        for (int ks = 0; ks < BK / 8; ks++) {
            int kk = ks * 8;
            int r0 = m_off + gid;
            uint32_t a0 = f2tf32(As[r0 * APAD + kk + tig]);
            uint32_t a1 = f2tf32(As[(r0 + 8) * APAD + kk + tig]);
            uint32_t a2 = f2tf32(As[r0 * APAD + kk + tig + 4]);
            uint32_t a3 = f2tf32(As[(r0 + 8) * APAD + kk + tig + 4]);
#pragma unroll
            for (int nb = 0; nb < 8; nb++) {
                int n = n_off + nb * 8 + gid;
                uint32_t bb0 = f2tf32(Bs[n * APAD + kk + tig]);
                uint32_t bb1 = f2tf32(Bs[n * APAD + kk + tig + 4]);
                mma_tf32(acc[nb], a0, a1, a2, a3, bb0, bb1);
            }
        }
        __syncthreads();
    }

    // ---- epilogue: stage gate tile in shared ----
#pragma unroll
    for (int nb = 0; nb < 8; nb++) {
        int row = m_off + gid;
        int col = n_off + nb * 8 + tig * 2;
        Gs[row * GPAD + col]           = acc[nb].x;
        Gs[row * GPAD + col + 1]       = acc[nb].y;
        Gs[(row + 8) * GPAD + col]     = acc[nb].z;
        Gs[(row + 8) * GPAD + col + 1] = acc[nb].w;
    }
    __syncthreads();

    // ---- fused LSTM cell update: 64*32 = 2048 cells, 8 per thread ----
#pragma unroll
    for (int l = 0; l < 8; l++) {
        int cell = l * 256 + tid;
        int bl = cell >> 5;          // 0..63
        int jj = cell & 31;          // 0..31
        int bg = b0 + bl;
        int jg = j0 + jj;
        size_t xbase = ((size_t)t * BB + bg) * G4 + jg;

        float ig = Gs[bl * GPAD + jj]       + g_xg[xbase];
        float fg = Gs[bl * GPAD + 32 + jj]  + g_xg[xbase + 1024];
        float gg = Gs[bl * GPAD + 64 + jj]  + g_xg[xbase + 2048];
        float og = Gs[bl * GPAD + 96 + jj]  + g_xg[xbase + 3072];

        float si = 1.f / (1.f + expf(-ig));
        float sf = 1.f / (1.f + expf(-fg));
        float so = 1.f / (1.f + expf(-og));
        float tg = tanhf(gg);

        int hc = bg * HID + jg;
        float c = sf * g_c[hc] + si * tg;
        g_c[hc] = c;
        hout[hc] = so * tanhf(c);
    }
}

// ---------------- final FC + sigmoid (OUT = 1) ----------------
__global__ void final_fc(const float* __restrict__ fc_w,
                         const float* __restrict__ fc_b,
                         const float* __restrict__ h,
                         float* __restrict__ out)
{
    int bb = blockIdx.x;
    int tid = threadIdx.x;   // 128 threads
    float s = 0.f;
    for (int k = tid; k < HID; k += 128)
        s += h[bb * HID + k] * fc_w[k];
    __shared__ float red[128];
    red[tid] = s;
    __syncthreads();
    for (int off = 64; off > 0; off >>= 1) {
        if (tid < off) red[tid] += red[tid + off];
        __syncthreads();
    }
    if (tid == 0)
        out[bb] = 1.f / (1.f + expf(-(red[0] + fc_b[0])));
}

// ---------------- launch ----------------
extern "C" void kernel_launch(void* const* d_in, const int* in_sizes, int n_in,
                              void* d_out, int out_size)
{
    const void*  text = d_in[0];
    const float* emb  = (const float*)d_in[1];
    const float* w_ih = (const float*)d_in[2];
    const float* w_hh = (const float*)d_in[3];
    const float* b_ih = (const float*)d_in[4];
    const float* b_hh = (const float*)d_in[5];
    const float* fc_w = (const float*)d_in[6];
    const float* fc_b = (const float*)d_in[7];
    float* out = (float*)d_out;

    detect_dtype<<<1, 32>>>(text);
    zero_hc<<<(BB * HID + 255) / 256, 256>>>();

    dim3 g1(512, 32);
    embed_gemm<<<g1, 256>>>(text, emb, w_ih, b_ih, b_hh);

    float* h0;  cudaGetSymbolAddress((void**)&h0, g_hbuf);
    float* h1 = h0 + BB * HID;

    dim3 g2(4, 32);   // 4 batch tiles x 32 hidden tiles = 128 blocks
    for (int t = 0; t < TT; t++) {
        const float* hin = (t & 1) ? h1 : h0;
        float* hout      = (t & 1) ? h0 : h1;
        step_fused<<<g2, 256>>>(w_hh, hin, hout, t);
    }

    // after t=255 (odd), hout = h0
    final_fc<<<BB, 128>>>(fc_w, fc_b, h0, out);
}

// round 5
// speedup vs baseline: 2.4312x; 1.4970x over previous
#include <cuda_runtime.h>
#include <cuda_bf16.h>
#include <math.h>
#include <stdint.h>

#define VOCAB 50000
#define EMB   512
#define HID   1024
#define G4    4096   // 4*HID
#define TT    256
#define BB    256

// ---------------- device scratch ----------------
__device__ float g_xg[(size_t)TT * BB * G4];          // [T][B][4H] input gates (+biases)
__device__ __nv_bfloat16 g_hb[2][BB * HID];           // double-buffered hidden (bf16)
__device__ __nv_bfloat16 g_whh[(size_t)G4 * HID];     // bf16 copy of w_hh
__device__ float g_c[BB * HID];
__device__ int   g_is64;

// ---------------- helpers ----------------
__device__ __forceinline__ uint32_t smem_u32(const void* p) {
    uint32_t a;
    asm("{ .reg .u64 t; cvta.to.shared.u64 t, %1; cvt.u32.u64 %0, t; }" : "=r"(a) : "l"(p));
    return a;
}

__device__ __forceinline__ void cpasync16(uint32_t dst, const void* src) {
    asm volatile("cp.async.cg.shared.global [%0], [%1], 16;" :: "r"(dst), "l"(src));
}
#define CP_COMMIT()  asm volatile("cp.async.commit_group;" ::: "memory")
#define CP_WAIT(n)   asm volatile("cp.async.wait_group %0;" :: "n"(n) : "memory")

__device__ __forceinline__ void ldsm4(uint32_t& r0, uint32_t& r1, uint32_t& r2, uint32_t& r3,
                                      uint32_t addr) {
    asm volatile("ldmatrix.sync.aligned.m8n8.x4.shared.b16 {%0,%1,%2,%3}, [%4];"
                 : "=r"(r0), "=r"(r1), "=r"(r2), "=r"(r3) : "r"(addr));
}

__device__ __forceinline__ void mma_bf16(float4& d, const uint32_t a[4],
                                         uint32_t b0, uint32_t b1) {
    asm volatile("mma.sync.aligned.m16n8k16.row.col.f32.bf16.bf16.f32 "
        "{%0,%1,%2,%3}, {%4,%5,%6,%7}, {%8,%9}, {%0,%1,%2,%3};"
        : "+f"(d.x), "+f"(d.y), "+f"(d.z), "+f"(d.w)
        : "r"(a[0]), "r"(a[1]), "r"(a[2]), "r"(a[3]), "r"(b0), "r"(b1));
}

// ---------------- prep kernels ----------------
__global__ void detect_dtype(const void* text) {
    if (threadIdx.x == 0 && blockIdx.x == 0) {
        const long long* p = (const long long*)text;
        int ok = 1;
        for (int i = 0; i < 64; i++) {
            long long v = p[i];
            if (v < 0 || v >= VOCAB) ok = 0;
        }
        g_is64 = ok;
    }
}

__global__ void zero_hc() {
    int i = blockIdx.x * blockDim.x + threadIdx.x;
    if (i < BB * HID) {
        g_hb[0][i] = __float2bfloat16(0.f);
        g_hb[1][i] = __float2bfloat16(0.f);
        g_c[i] = 0.f;
    }
}

__global__ void conv_whh(const float* __restrict__ w) {
    size_t i = ((size_t)blockIdx.x * 256 + threadIdx.x) * 4;
    float4 v = *(const float4*)(w + i);
    *(__nv_bfloat162*)(g_whh + i)     = __floats2bfloat162_rn(v.x, v.y);
    *(__nv_bfloat162*)(g_whh + i + 2) = __floats2bfloat162_rn(v.z, v.w);
}

// ---------------- fused embedding gather + input GEMM (fp32 SIMT) ----------------
__global__ __launch_bounds__(256) void embed_gemm(
    const void* __restrict__ text,
    const float* __restrict__ emb,
    const float* __restrict__ w_ih,
    const float* __restrict__ b_ih,
    const float* __restrict__ b_hh)
{
    __shared__ __align__(16) float As[16][128];
    __shared__ __align__(16) float Bs[16][128];
    __shared__ int toks[128];

    const int tid = threadIdx.x;
    const int m0 = blockIdx.x * 128;
    const int n0 = blockIdx.y * 128;

    if (tid < 128) {
        int m = m0 + tid;
        toks[tid] = g_is64 ? (int)((const long long*)text)[m]
                           : ((const int*)text)[m];
    }
    __syncthreads();

    const int tx = tid & 15;
    const int ty = tid >> 4;

    float acc[8][8];
#pragma unroll
    for (int i = 0; i < 8; i++)
#pragma unroll
        for (int j = 0; j < 8; j++) acc[i][j] = 0.f;

    for (int k0 = 0; k0 < EMB; k0 += 16) {
#pragma unroll
        for (int l = 0; l < 2; l++) {
            int i  = tid + l * 256;
            int m  = i >> 2;
            int kq = (i & 3) << 2;
            float4 va = *(const float4*)(emb + (size_t)toks[m] * EMB + k0 + kq);
            As[kq + 0][m] = va.x; As[kq + 1][m] = va.y;
            As[kq + 2][m] = va.z; As[kq + 3][m] = va.w;
            float4 vb = *(const float4*)(w_ih + (size_t)(n0 + m) * EMB + k0 + kq);
            Bs[kq + 0][m] = vb.x; Bs[kq + 1][m] = vb.y;
            Bs[kq + 2][m] = vb.z; Bs[kq + 3][m] = vb.w;
        }
        __syncthreads();

#pragma unroll
        for (int k = 0; k < 16; k++) {
            float4 a0 = *(const float4*)&As[k][ty * 4];
            float4 a1 = *(const float4*)&As[k][64 + ty * 4];
            float4 b0 = *(const float4*)&Bs[k][tx * 4];
            float4 b1 = *(const float4*)&Bs[k][64 + tx * 4];
            float a[8] = {a0.x, a0.y, a0.z, a0.w, a1.x, a1.y, a1.z, a1.w};
            float b[8] = {b0.x, b0.y, b0.z, b0.w, b1.x, b1.y, b1.z, b1.w};
#pragma unroll
            for (int i = 0; i < 8; i++)
#pragma unroll
                for (int j = 0; j < 8; j++) acc[i][j] += a[i] * b[j];
        }
        __syncthreads();
    }

#pragma unroll
    for (int i = 0; i < 8; i++) {
        int row = (i < 4) ? (ty * 4 + i) : (64 + ty * 4 + (i - 4));
        int m = m0 + row;
        int bb = m >> 8;
        int t  = m & 255;
        size_t base = ((size_t)t * BB + bb) * G4 + n0;
#pragma unroll
        for (int j = 0; j < 8; j++) {
            int col = (j < 4) ? (tx * 4 + j) : (64 + tx * 4 + (j - 4));
            g_xg[base + col] = acc[i][j] + b_ih[n0 + col] + b_hh[n0 + col];
        }
    }
}

// ---------------- bf16 HMMA recurrent step ----------------
// Per CTA: BM=64 batch rows, BN=128 (4 gates x 32 hid), K=1024 in 32 chunks of 32.
// smem rows at 80B pitch (conflict-free ldmatrix). cp.async double buffering.
// Warps: 2(M) x 4(N); warp tile 32x32; per chunk 16 MMA + 8 LDSM.x4 per warp.
#define BM    64
#define BJ    32
#define BN    128
#define BK    32
#define PITCH 80
#define SA0   0
#define SA1   5120
#define SB0   10240
#define SB1   20480
#define GSP   129
#define SM_BYTES 33024   // max(GEMM 30720, Gs 64*129*4)

__global__ __launch_bounds__(256) void step_mma(
    const __nv_bfloat16* __restrict__ hin,
    __nv_bfloat16* __restrict__ hout,
    int t)
{
    __shared__ __align__(16) char smem[SM_BYTES];
    const uint32_t sb = smem_u32(smem);

    const int tid  = threadIdx.x;
    const int lane = tid & 31;
    const int warp = tid >> 5;
    const int wm   = warp >> 2;          // 0..1
    const int wn   = warp & 3;           // 0..3
    const int b0 = blockIdx.x * BM;      // grid.x = 4
    const int j0 = blockIdx.y * BJ;      // grid.y = 32

    // fill one K-chunk into buffer `buf` via cp.async
    auto issue = [&](int buf, int chunk) {
        const int k0 = chunk * BK;
        {   // A: 64 rows x 64B = 256 x 16B, 1 per thread
            int r = tid >> 2, q = (tid & 3) << 3;
            cpasync16(sb + (buf ? SA1 : SA0) + r * PITCH + q * 2,
                      hin + (size_t)(b0 + r) * HID + k0 + q);
        }
#pragma unroll
        for (int l = 0; l < 2; l++) {   // B: 128 rows x 64B = 512 x 16B
            int idx = tid + l * 256;
            int r = idx >> 2, q = (idx & 3) << 3;
            int nrow = ((r >> 5) << 10) + j0 + (r & 31);   // gate*1024 + j0 + jj
            cpasync16(sb + (buf ? SB1 : SB0) + r * PITCH + q * 2,
                      g_whh + (size_t)nrow * HID + k0 + q);
        }
        CP_COMMIT();
    };

    float4 acc[2][4];
#pragma unroll
    for (int i = 0; i < 2; i++)
#pragma unroll
        for (int j = 0; j < 4; j++) acc[i][j] = make_float4(0.f, 0.f, 0.f, 0.f);

    issue(0, 0);

    const uint32_t laneoff = (uint32_t)((lane & 15) * PITCH + (lane >> 4) * 16);

    for (int c = 0; c < 32; c++) {
        const int buf = c & 1;
        if (c + 1 < 32) { issue(buf ^ 1, c + 1); CP_WAIT(1); }
        else            { CP_WAIT(0); }
        __syncthreads();

        const uint32_t aB = sb + (buf ? SA1 : SA0);
        const uint32_t bB = sb + (buf ? SB1 : SB0);

#pragma unroll
        for (int ks = 0; ks < 2; ks++) {
            uint32_t a[2][4];
#pragma unroll
            for (int mi = 0; mi < 2; mi++) {
                uint32_t ad = aB + (uint32_t)((wm * 32 + mi * 16) * PITCH + ks * 32) + laneoff;
                ldsm4(a[mi][0], a[mi][1], a[mi][2], a[mi][3], ad);
            }
#pragma unroll
            for (int nj = 0; nj < 2; nj++) {
                uint32_t f0, f1, f2, f3;
                uint32_t bd = bB + (uint32_t)((wn * 32 + nj * 16) * PITCH + ks * 32) + laneoff;
                ldsm4(f0, f1, f2, f3, bd);
#pragma unroll
                for (int mi = 0; mi < 2; mi++) {
                    mma_bf16(acc[mi][nj * 2],     a[mi], f0, f2);
                    mma_bf16(acc[mi][nj * 2 + 1], a[mi], f1, f3);
                }
            }
        }
        __syncthreads();   // buffer free before re-issue
    }

    // ---- stage 64x128 gate tile into smem (overlay) ----
    float* Gs = (float*)smem;
    const int gid = lane >> 2;
    const int tig = lane & 3;
#pragma unroll
    for (int mi = 0; mi < 2; mi++) {
#pragma unroll
        for (int q = 0; q < 4; q++) {
            int R = wm * 32 + mi * 16 + gid;
            int C = wn * 32 + (q >> 1) * 16 + (q & 1) * 8 + tig * 2;
            float4 v = acc[mi][q];
            Gs[R * GSP + C]           = v.x;
            Gs[R * GSP + C + 1]       = v.y;
            Gs[(R + 8) * GSP + C]     = v.z;
            Gs[(R + 8) * GSP + C + 1] = v.w;
        }
    }
    __syncthreads();

    // ---- fused LSTM cell update: 64*32 = 2048 cells, 8 per thread ----
#pragma unroll
    for (int l = 0; l < 8; l++) {
        int id = l * 256 + tid;
        int m  = id >> 5;
        int jj = id & 31;
        int bg = b0 + m;
        int jg = j0 + jj;
        size_t xb = ((size_t)t * BB + bg) * G4 + jg;

        float ig = Gs[m * GSP + jj]      + g_xg[xb];
        float fg = Gs[m * GSP + 32 + jj] + g_xg[xb + 1024];
        float gg = Gs[m * GSP + 64 + jj] + g_xg[xb + 2048];
        float og = Gs[m * GSP + 96 + jj] + g_xg[xb + 3072];

        float si = 1.f / (1.f + expf(-ig));
        float sf = 1.f / (1.f + expf(-fg));
        float so = 1.f / (1.f + expf(-og));
        float tg = tanhf(gg);

        int hc = bg * HID + jg;
        float c2 = sf * g_c[hc] + si * tg;
        g_c[hc] = c2;
        hout[hc] = __float2bfloat16(so * tanhf(c2));
    }
}

// ---------------- final FC + sigmoid (OUT = 1) ----------------
__global__ void final_fc(const float* __restrict__ fc_w,
                         const float* __restrict__ fc_b,
                         const __nv_bfloat16* __restrict__ h,
                         float* __restrict__ out)
{
    int bb = blockIdx.x;
    int tid = threadIdx.x;   // 128 threads
    float s = 0.f;
    for (int k = tid; k < HID; k += 128)
        s += __bfloat162float(h[bb * HID + k]) * fc_w[k];
    __shared__ float red[128];
    red[tid] = s;
    __syncthreads();
    for (int off = 64; off > 0; off >>= 1) {
        if (tid < off) red[tid] += red[tid + off];
        __syncthreads();
    }
    if (tid == 0)
        out[bb] = 1.f / (1.f + expf(-(red[0] + fc_b[0])));
}

// ---------------- launch ----------------
extern "C" void kernel_launch(void* const* d_in, const int* in_sizes, int n_in,
                              void* d_out, int out_size)
{
    const void*  text = d_in[0];
    const float* emb  = (const float*)d_in[1];
    const float* w_ih = (const float*)d_in[2];
    const float* w_hh = (const float*)d_in[3];
    const float* b_ih = (const float*)d_in[4];
    const float* b_hh = (const float*)d_in[5];
    const float* fc_w = (const float*)d_in[6];
    const float* fc_b = (const float*)d_in[7];
    float* out = (float*)d_out;

    detect_dtype<<<1, 32>>>(text);
    zero_hc<<<(BB * HID + 255) / 256, 256>>>();
    conv_whh<<<(G4 * HID) / 1024, 256>>>(w_hh);

    dim3 g1(512, 32);
    embed_gemm<<<g1, 256>>>(text, emb, w_ih, b_ih, b_hh);

    __nv_bfloat16* h0;
    cudaGetSymbolAddress((void**)&h0, g_hb);
    __nv_bfloat16* h1 = h0 + BB * HID;

    dim3 g2(4, 32);   // 4 batch tiles x 32 hidden tiles = 128 CTAs
    for (int t = 0; t < TT; t++) {
        const __nv_bfloat16* hin = (t & 1) ? h1 : h0;
        __nv_bfloat16* hout      = (t & 1) ? h0 : h1;
        step_mma<<<g2, 256>>>(hin, hout, t);
    }

    // after t=255 (odd), hout = h0
    final_fc<<<BB, 128>>>(fc_w, fc_b, h0, out);
}

// round 6
// speedup vs baseline: 2.6833x; 1.1037x over previous
#include <cuda_runtime.h>
#include <cuda_bf16.h>
#include <math.h>
#include <stdint.h>

#define VOCAB 50000
#define EMB   512
#define HID   1024
#define G4    4096   // 4*HID
#define TT    256
#define BB    256

// ---------------- device scratch ----------------
__device__ float g_xg[(size_t)TT * BB * G4];          // [T][B][4H] input gates (+biases)
__device__ __nv_bfloat16 g_hb[2][BB * HID];           // double-buffered hidden (bf16)
__device__ __nv_bfloat16 g_whh[(size_t)G4 * HID];     // bf16 copy of w_hh
__device__ float g_c[BB * HID];
__device__ int   g_is64;
__device__ unsigned g_bar;                            // persistent-kernel grid barrier

// ---------------- helpers ----------------
__device__ __forceinline__ uint32_t smem_u32(const void* p) {
    uint32_t a;
    asm("{ .reg .u64 t; cvta.to.shared.u64 t, %1; cvt.u32.u64 %0, t; }" : "=r"(a) : "l"(p));
    return a;
}
__device__ __forceinline__ void cpasync16(uint32_t dst, const void* src) {
    asm volatile("cp.async.cg.shared.global [%0], [%1], 16;" :: "r"(dst), "l"(src));
}
#define CP_COMMIT()  asm volatile("cp.async.commit_group;" ::: "memory")
#define CP_WAIT(n)   asm volatile("cp.async.wait_group %0;" :: "n"(n) : "memory")

__device__ __forceinline__ void ldsm4(uint32_t& r0, uint32_t& r1, uint32_t& r2, uint32_t& r3,
                                      uint32_t addr) {
    asm volatile("ldmatrix.sync.aligned.m8n8.x4.shared.b16 {%0,%1,%2,%3}, [%4];"
                 : "=r"(r0), "=r"(r1), "=r"(r2), "=r"(r3) : "r"(addr));
}
__device__ __forceinline__ void mma_bf16(float4& d, const uint32_t a[4],
                                         uint32_t b0, uint32_t b1) {
    asm volatile("mma.sync.aligned.m16n8k16.row.col.f32.bf16.bf16.f32 "
        "{%0,%1,%2,%3}, {%4,%5,%6,%7}, {%8,%9}, {%0,%1,%2,%3};"
        : "+f"(d.x), "+f"(d.y), "+f"(d.z), "+f"(d.w)
        : "r"(a[0]), "r"(a[1]), "r"(a[2]), "r"(a[3]), "r"(b0), "r"(b1));
}

// ---------------- prep kernels ----------------
__global__ void detect_dtype(const void* text) {
    if (threadIdx.x == 0 && blockIdx.x == 0) {
        const long long* p = (const long long*)text;
        int ok = 1;
        for (int i = 0; i < 64; i++) {
            long long v = p[i];
            if (v < 0 || v >= VOCAB) ok = 0;
        }
        g_is64 = ok;
    }
}

__global__ void zero_hc() {
    int i = blockIdx.x * blockDim.x + threadIdx.x;
    if (i == 0) g_bar = 0u;
    if (i < BB * HID) {
        g_hb[0][i] = __float2bfloat16(0.f);
        g_hb[1][i] = __float2bfloat16(0.f);
        g_c[i] = 0.f;
    }
}

__global__ void conv_whh(const float* __restrict__ w) {
    size_t i = ((size_t)blockIdx.x * 256 + threadIdx.x) * 4;
    float4 v = *(const float4*)(w + i);
    *(__nv_bfloat162*)(g_whh + i)     = __floats2bfloat162_rn(v.x, v.y);
    *(__nv_bfloat162*)(g_whh + i + 2) = __floats2bfloat162_rn(v.z, v.w);
}

// ---------------- fused embedding gather + input GEMM (fp32 SIMT) ----------------
__global__ __launch_bounds__(256) void embed_gemm(
    const void* __restrict__ text,
    const float* __restrict__ emb,
    const float* __restrict__ w_ih,
    const float* __restrict__ b_ih,
    const float* __restrict__ b_hh)
{
    __shared__ __align__(16) float As[16][128];
    __shared__ __align__(16) float Bs[16][128];
    __shared__ int toks[128];

    const int tid = threadIdx.x;
    const int m0 = blockIdx.x * 128;
    const int n0 = blockIdx.y * 128;

    if (tid < 128) {
        int m = m0 + tid;
        toks[tid] = g_is64 ? (int)((const long long*)text)[m]
                           : ((const int*)text)[m];
    }
    __syncthreads();

    const int tx = tid & 15;
    const int ty = tid >> 4;

    float acc[8][8];
#pragma unroll
    for (int i = 0; i < 8; i++)
#pragma unroll
        for (int j = 0; j < 8; j++) acc[i][j] = 0.f;

    for (int k0 = 0; k0 < EMB; k0 += 16) {
#pragma unroll
        for (int l = 0; l < 2; l++) {
            int i  = tid + l * 256;
            int m  = i >> 2;
            int kq = (i & 3) << 2;
            float4 va = *(const float4*)(emb + (size_t)toks[m] * EMB + k0 + kq);
            As[kq + 0][m] = va.x; As[kq + 1][m] = va.y;
            As[kq + 2][m] = va.z; As[kq + 3][m] = va.w;
            float4 vb = *(const float4*)(w_ih + (size_t)(n0 + m) * EMB + k0 + kq);
            Bs[kq + 0][m] = vb.x; Bs[kq + 1][m] = vb.y;
            Bs[kq + 2][m] = vb.z; Bs[kq + 3][m] = vb.w;
        }
        __syncthreads();

#pragma unroll
        for (int k = 0; k < 16; k++) {
            float4 a0 = *(const float4*)&As[k][ty * 4];
            float4 a1 = *(const float4*)&As[k][64 + ty * 4];
            float4 b0 = *(const float4*)&Bs[k][tx * 4];
            float4 b1 = *(const float4*)&Bs[k][64 + tx * 4];
            float a[8] = {a0.x, a0.y, a0.z, a0.w, a1.x, a1.y, a1.z, a1.w};
            float b[8] = {b0.x, b0.y, b0.z, b0.w, b1.x, b1.y, b1.z, b1.w};
#pragma unroll
            for (int i = 0; i < 8; i++)
#pragma unroll
                for (int j = 0; j < 8; j++) acc[i][j] += a[i] * b[j];
        }
        __syncthreads();
    }

#pragma unroll
    for (int i = 0; i < 8; i++) {
        int row = (i < 4) ? (ty * 4 + i) : (64 + ty * 4 + (i - 4));
        int m = m0 + row;
        int bb = m >> 8;
        int t  = m & 255;
        size_t base = ((size_t)t * BB + bb) * G4 + n0;
#pragma unroll
        for (int j = 0; j < 8; j++) {
            int col = (j < 4) ? (tx * 4 + j) : (64 + tx * 4 + (j - 4));
            g_xg[base + col] = acc[i][j] + b_ih[n0 + col] + b_hh[n0 + col];
        }
    }
}

// ---------------- persistent recurrent kernel ----------------
// Grid = 128 CTAs (2 batch tiles x 64 hid tiles), all co-resident (<=148 SMs).
// Per CTA: BM=128 batch rows, 64 gate rows (4 gates x BJ=16 hid). w_hh slice
// (64 x 1024 bf16) stays RESIDENT in smem for all 256 steps; per step only the
// h tile streams via cp.async.cg (L1-bypass -> always L2-coherent).
#define BM   128
#define BJ   16
#define BNr  64            // gate rows per CTA = 4*BJ
#define BK   128           // K chunk
#define PA   272           // A row pitch bytes (68 words, %32 = 4 -> conflict-free)
#define PB   2064          // B row pitch bytes (516 words, %32 = 4 -> conflict-free)
#define SMB  0             // B resident: 64 * 2064   = 132096
#define SMA0 132096        // A buf 0:    128 * 272   = 34816
#define SMA1 166912        // A buf 1
#define SMTOT 201728
#define GSP  68            // Gs pitch (floats); Gs = 128*68*4 = 34816 B, overlays A0

__global__ __launch_bounds__(256, 1) void lstm_persist()
{
    extern __shared__ __align__(16) char smem[];
    const uint32_t sb = smem_u32(smem);

    const int tid  = threadIdx.x;
    const int lane = tid & 31;
    const int warp = tid >> 5;
    const int wm   = warp >> 1;          // 0..3  (M tiles of 32)
    const int wn   = warp & 1;           // 0..1  (N tiles of 32)
    const int cta  = blockIdx.x;
    const int b0   = (cta >> 6) * BM;    // batch tile base
    const int j0   = (cta & 63) * BJ;    // hidden tile base

    // ---- load resident w_hh slice: 64 rows x 2048B = 8192 x 16B ----
#pragma unroll
    for (int l = 0; l < 32; l++) {
        int idx = l * 256 + tid;
        int r = idx >> 7;                // 0..63 (= gate*16 + jj)
        int q = idx & 127;               // 16B column
        int grow = ((r >> 4) << 10) + j0 + (r & 15);
        cpasync16(sb + SMB + r * PB + q * 16, g_whh + (size_t)grow * HID + q * 8);
    }
    CP_COMMIT();
    CP_WAIT(0);
    __syncthreads();

    const uint32_t laneoff = (uint32_t)((lane & 15) * PA + (lane >> 4) * 16);
    const uint32_t laneoffB = (uint32_t)((lane & 15) * PB + (lane >> 4) * 16);

    for (int t = 0; t < TT; t++) {
        const __nv_bfloat16* hin = g_hb[t & 1];
        __nv_bfloat16* hout      = g_hb[(t + 1) & 1];

        // issue A chunks 0,1
#pragma unroll
        for (int pc = 0; pc < 2; pc++) {
#pragma unroll
            for (int l = 0; l < 8; l++) {
                int idx = l * 256 + tid;
                int r = idx >> 4, q = idx & 15;
                cpasync16(sb + (pc ? SMA1 : SMA0) + r * PA + q * 16,
                          hin + (size_t)(b0 + r) * HID + pc * BK + q * 8);
            }
            CP_COMMIT();
        }

        float4 acc[2][4];
#pragma unroll
        for (int i = 0; i < 2; i++)
#pragma unroll
            for (int j = 0; j < 4; j++) acc[i][j] = make_float4(0.f, 0.f, 0.f, 0.f);

        for (int c = 0; c < 8; c++) {
            if (c < 7) CP_WAIT(1);
            else       CP_WAIT(0);
            __syncthreads();

            const uint32_t aB = sb + ((c & 1) ? SMA1 : SMA0);
            const uint32_t bB = sb + SMB + (uint32_t)(c * 256);

#pragma unroll
            for (int ks = 0; ks < 8; ks++) {
                uint32_t a[2][4];
#pragma unroll
                for (int mi = 0; mi < 2; mi++) {
                    uint32_t ad = aB + (uint32_t)((wm * 32 + mi * 16) * PA + ks * 32) + laneoff;
                    ldsm4(a[mi][0], a[mi][1], a[mi][2], a[mi][3], ad);
                }
#pragma unroll
                for (int nj = 0; nj < 2; nj++) {
                    uint32_t f0, f1, f2, f3;
                    uint32_t bd = bB + (uint32_t)((wn * 32 + nj * 16) * PB + ks * 32) + laneoffB;
                    ldsm4(f0, f1, f2, f3, bd);
#pragma unroll
                    for (int mi = 0; mi < 2; mi++) {
                        mma_bf16(acc[mi][nj * 2],     a[mi], f0, f2);
                        mma_bf16(acc[mi][nj * 2 + 1], a[mi], f1, f3);
                    }
                }
            }
            __syncthreads();           // buffer consumed before refill
            if (c + 2 < 8) {
#pragma unroll
                for (int l = 0; l < 8; l++) {
                    int idx = l * 256 + tid;
                    int r = idx >> 4, q = idx & 15;
                    cpasync16(sb + ((c & 1) ? SMA1 : SMA0) + r * PA + q * 16,
                              hin + (size_t)(b0 + r) * HID + (c + 2) * BK + q * 8);
                }
                CP_COMMIT();
            }
        }

        // ---- stage 128x64 gate tile into smem (overlays A0) ----
        float* Gs = (float*)(smem + SMA0);
        const int gid = lane >> 2;
        const int tig = lane & 3;
#pragma unroll
        for (int mi = 0; mi < 2; mi++) {
#pragma unroll
            for (int q = 0; q < 4; q++) {
                int R = wm * 32 + mi * 16 + gid;
                int C = wn * 32 + (q >> 1) * 16 + (q & 1) * 8 + tig * 2;
                float4 v = acc[mi][q];
                Gs[R * GSP + C]           = v.x;
                Gs[R * GSP + C + 1]       = v.y;
                Gs[(R + 8) * GSP + C]     = v.z;
                Gs[(R + 8) * GSP + C + 1] = v.w;
            }
        }
        __syncthreads();

        // ---- fused LSTM cell update: 128*16 = 2048 cells, 8 per thread ----
#pragma unroll
        for (int l = 0; l < 8; l++) {
            int id = l * 256 + tid;
            int m  = id >> 4;
            int jj = id & 15;
            int bg = b0 + m;
            int jg = j0 + jj;
            size_t xb = ((size_t)t * BB + bg) * G4 + jg;

            float ig = Gs[m * GSP + jj]      + g_xg[xb];
            float fg = Gs[m * GSP + 16 + jj] + g_xg[xb + 1024];
            float gg = Gs[m * GSP + 32 + jj] + g_xg[xb + 2048];
            float og = Gs[m * GSP + 48 + jj] + g_xg[xb + 3072];

            float si = 1.f / (1.f + __expf(-ig));
            float sf = 1.f / (1.f + __expf(-fg));
            float so = 1.f / (1.f + __expf(-og));
            float tg = tanhf(gg);

            int hc = bg * HID + jg;
            float c2 = sf * g_c[hc] + si * tg;
            g_c[hc] = c2;
            hout[hc] = __float2bfloat16(so * tanhf(c2));
        }

        // ---- grid barrier (skip after last step) ----
        if (t + 1 < TT) {
            __threadfence();
            __syncthreads();
            if (tid == 0) {
                unsigned target = 128u * (unsigned)(t + 1);
                atomicAdd(&g_bar, 1u);
                while (atomicAdd(&g_bar, 0u) < target) __nanosleep(64);
                __threadfence();
            }
            __syncthreads();
        }
    }
}

// ---------------- final FC + sigmoid (OUT = 1) ----------------
__global__ void final_fc(const float* __restrict__ fc_w,
                         const float* __restrict__ fc_b,
                         const __nv_bfloat16* __restrict__ h,
                         float* __restrict__ out)
{
    int bb = blockIdx.x;
    int tid = threadIdx.x;   // 128 threads
    float s = 0.f;
    for (int k = tid; k < HID; k += 128)
        s += __bfloat162float(h[bb * HID + k]) * fc_w[k];
    __shared__ float red[128];
    red[tid] = s;
    __syncthreads();
    for (int off = 64; off > 0; off >>= 1) {
        if (tid < off) red[tid] += red[tid + off];
        __syncthreads();
    }
    if (tid == 0)
        out[bb] = 1.f / (1.f + expf(-(red[0] + fc_b[0])));
}

// ---------------- launch ----------------
extern "C" void kernel_launch(void* const* d_in, const int* in_sizes, int n_in,
                              void* d_out, int out_size)
{
    const void*  text = d_in[0];
    const float* emb  = (const float*)d_in[1];
    const float* w_ih = (const float*)d_in[2];
    const float* w_hh = (const float*)d_in[3];
    const float* b_ih = (const float*)d_in[4];
    const float* b_hh = (const float*)d_in[5];
    const float* fc_w = (const float*)d_in[6];
    const float* fc_b = (const float*)d_in[7];
    float* out = (float*)d_out;

    detect_dtype<<<1, 32>>>(text);
    zero_hc<<<(BB * HID + 255) / 256, 256>>>();
    conv_whh<<<(G4 * HID) / 1024, 256>>>(w_hh);

    dim3 g1(512, 32);
    embed_gemm<<<g1, 256>>>(text, emb, w_ih, b_ih, b_hh);

    cudaFuncSetAttribute(lstm_persist, cudaFuncAttributeMaxDynamicSharedMemorySize, SMTOT);
    lstm_persist<<<128, 256, SMTOT>>>();

    // after t=255 (odd), final h is in g_hb[0]
    __nv_bfloat16* h0;
    cudaGetSymbolAddress((void**)&h0, g_hb);
    final_fc<<<BB, 128>>>(fc_w, fc_b, h0, out);
}

// round 7
// speedup vs baseline: 4.6130x; 1.7192x over previous
#include <cuda_runtime.h>
#include <cuda_bf16.h>
#include <math.h>
#include <stdint.h>

#define VOCAB 50000
#define EMB   512
#define HID   1024
#define G4    4096   // 4*HID
#define TT    256
#define BB    256

// ---------------- device scratch ----------------
__device__ float g_xg[(size_t)TT * BB * G4];          // [T][B][4H] input gates (+biases)
__device__ __nv_bfloat16 g_hb[2][BB * HID];           // double-buffered hidden (bf16)
__device__ __nv_bfloat16 g_whh[(size_t)G4 * HID];     // bf16 w_hh
__device__ __nv_bfloat16 g_wih[(size_t)G4 * EMB];     // bf16 w_ih
__device__ __nv_bfloat16 g_emb[(size_t)VOCAB * EMB];  // bf16 embedding table
__device__ float g_c[BB * HID];
__device__ int   g_is64;
__device__ unsigned g_bar;                            // persistent-kernel grid barrier

// ---------------- helpers ----------------
__device__ __forceinline__ uint32_t smem_u32(const void* p) {
    uint32_t a;
    asm("{ .reg .u64 t; cvta.to.shared.u64 t, %1; cvt.u32.u64 %0, t; }" : "=r"(a) : "l"(p));
    return a;
}
__device__ __forceinline__ void cpasync16(uint32_t dst, const void* src) {
    asm volatile("cp.async.cg.shared.global [%0], [%1], 16;" :: "r"(dst), "l"(src));
}
#define CP_COMMIT()  asm volatile("cp.async.commit_group;" ::: "memory")
#define CP_WAIT(n)   asm volatile("cp.async.wait_group %0;" :: "n"(n) : "memory")

__device__ __forceinline__ void ldsm4(uint32_t& r0, uint32_t& r1, uint32_t& r2, uint32_t& r3,
                                      uint32_t addr) {
    asm volatile("ldmatrix.sync.aligned.m8n8.x4.shared.b16 {%0,%1,%2,%3}, [%4];"
                 : "=r"(r0), "=r"(r1), "=r"(r2), "=r"(r3) : "r"(addr));
}
__device__ __forceinline__ void mma_bf16(float4& d, const uint32_t a[4],
                                         uint32_t b0, uint32_t b1) {
    asm volatile("mma.sync.aligned.m16n8k16.row.col.f32.bf16.bf16.f32 "
        "{%0,%1,%2,%3}, {%4,%5,%6,%7}, {%8,%9}, {%0,%1,%2,%3};"
        : "+f"(d.x), "+f"(d.y), "+f"(d.z), "+f"(d.w)
        : "r"(a[0]), "r"(a[1]), "r"(a[2]), "r"(a[3]), "r"(b0), "r"(b1));
}

// ---------------- prep kernels ----------------
__global__ void detect_dtype(const void* text) {
    if (threadIdx.x == 0 && blockIdx.x == 0) {
        const long long* p = (const long long*)text;
        int ok = 1;
        for (int i = 0; i < 64; i++) {
            long long v = p[i];
            if (v < 0 || v >= VOCAB) ok = 0;
        }
        g_is64 = ok;
    }
}

__global__ void zero_hc() {
    int i = blockIdx.x * blockDim.x + threadIdx.x;
    if (i == 0) g_bar = 0u;
    if (i < BB * HID) {
        g_hb[0][i] = __float2bfloat16(0.f);
        g_hb[1][i] = __float2bfloat16(0.f);
        g_c[i] = 0.f;
    }
}

__global__ void conv_f2b(const float* __restrict__ src, __nv_bfloat16* __restrict__ dst) {
    size_t i = ((size_t)blockIdx.x * 256 + threadIdx.x) * 4;
    float4 v = *(const float4*)(src + i);
    *(__nv_bfloat162*)(dst + i)     = __floats2bfloat162_rn(v.x, v.y);
    *(__nv_bfloat162*)(dst + i + 2) = __floats2bfloat162_rn(v.z, v.w);
}

// ---------------- bf16 MMA embedding gather + input GEMM ----------------
// Per CTA: 128 tokens x 128 gates, K = 512 in 16 chunks of 32.
// Warps 4(M) x 2(N); warp tile 32 x 64. Same fragment scheme as the
// (correctness-proven) R5 step_mma: pitch-80 rows, ldsm.x4, m16n8k16.
#define EPITCH 80
#define ESA0   0
#define ESA1   10240
#define ESB0   20480
#define ESB1   30720
#define ESEND  40960

__global__ __launch_bounds__(256) void embed_mma(
    const void* __restrict__ text,
    const float* __restrict__ b_ih,
    const float* __restrict__ b_hh)
{
    __shared__ __align__(16) char smem[ESEND];
    __shared__ int   toks[128];
    __shared__ float bias[128];
    const uint32_t sb = smem_u32(smem);

    const int tid  = threadIdx.x;
    const int lane = tid & 31;
    const int warp = tid >> 5;
    const int wm   = warp >> 1;          // 0..3 (M tiles of 32)
    const int wn   = warp & 1;           // 0..1 (N tiles of 64)
    const int m0 = blockIdx.x * 128;     // token tile (grid.x = 512)
    const int n0 = blockIdx.y * 128;     // gate tile  (grid.y = 32)

    if (tid < 128) {
        int m = m0 + tid;
        toks[tid] = g_is64 ? (int)((const long long*)text)[m]
                           : ((const int*)text)[m];
        bias[tid] = b_ih[n0 + tid] + b_hh[n0 + tid];
    }
    __syncthreads();

    // issue one K-chunk (32 bf16) into buffer `buf`
    auto issue = [&](int buf, int chunk) {
        const int k0 = chunk * 32;
#pragma unroll
        for (int l = 0; l < 2; l++) {    // A: 128 rows x 64B = 512 x 16B
            int idx = l * 256 + tid;
            int r = idx >> 2, q = (idx & 3) << 3;
            cpasync16(sb + (buf ? ESA1 : ESA0) + r * EPITCH + q * 2,
                      g_emb + (size_t)toks[r] * EMB + k0 + q);
        }
#pragma unroll
        for (int l = 0; l < 2; l++) {    // B: 128 rows x 64B
            int idx = l * 256 + tid;
            int r = idx >> 2, q = (idx & 3) << 3;
            cpasync16(sb + (buf ? ESB1 : ESB0) + r * EPITCH + q * 2,
                      g_wih + (size_t)(n0 + r) * EMB + k0 + q);
        }
        CP_COMMIT();
    };

    float4 acc[2][8];
#pragma unroll
    for (int i = 0; i < 2; i++)
#pragma unroll
        for (int j = 0; j < 8; j++) acc[i][j] = make_float4(0.f, 0.f, 0.f, 0.f);

    issue(0, 0);
    issue(1, 1);

    const uint32_t laneoff = (uint32_t)((lane & 15) * EPITCH + (lane >> 4) * 16);

    for (int c = 0; c < 16; c++) {
        if (c < 15) CP_WAIT(1);
        else        CP_WAIT(0);
        __syncthreads();

        const uint32_t aB = sb + ((c & 1) ? ESA1 : ESA0);
        const uint32_t bB = sb + ((c & 1) ? ESB1 : ESB0);

#pragma unroll
        for (int ks = 0; ks < 2; ks++) {
            uint32_t a[2][4];
#pragma unroll
            for (int mi = 0; mi < 2; mi++) {
                uint32_t ad = aB + (uint32_t)((wm * 32 + mi * 16) * EPITCH + ks * 32) + laneoff;
                ldsm4(a[mi][0], a[mi][1], a[mi][2], a[mi][3], ad);
            }
#pragma unroll
            for (int nj = 0; nj < 4; nj++) {
                uint32_t f0, f1, f2, f3;
                uint32_t bd = bB + (uint32_t)((wn * 64 + nj * 16) * EPITCH + ks * 32) + laneoff;
                ldsm4(f0, f1, f2, f3, bd);
#pragma unroll
                for (int mi = 0; mi < 2; mi++) {
                    mma_bf16(acc[mi][nj * 2],     a[mi], f0, f2);
                    mma_bf16(acc[mi][nj * 2 + 1], a[mi], f1, f3);
                }
            }
        }
        __syncthreads();
        if (c + 2 < 16) issue(c & 1, c + 2);
    }

    // ---- epilogue: direct scatter to g_xg [T][B][4H] with bias ----
    const int gid = lane >> 2;
    const int tig = lane & 3;
#pragma unroll
    for (int mi = 0; mi < 2; mi++) {
        int R = wm * 32 + mi * 16 + gid;
        int mA = m0 + R;
        int mB = mA + 8;
        size_t baseA = ((size_t)(mA & 255) * BB + (mA >> 8)) * G4 + n0;
        size_t baseB = ((size_t)(mB & 255) * BB + (mB >> 8)) * G4 + n0;
#pragma unroll
        for (int nj = 0; nj < 4; nj++) {
#pragma unroll
            for (int h = 0; h < 2; h++) {
                float4 v = acc[mi][nj * 2 + h];
                int C = wn * 64 + nj * 16 + h * 8 + tig * 2;
                g_xg[baseA + C]     = v.x + bias[C];
                g_xg[baseA + C + 1] = v.y + bias[C + 1];
                g_xg[baseB + C]     = v.z + bias[C];
                g_xg[baseB + C + 1] = v.w + bias[C + 1];
            }
        }
    }
}

// ---------------- persistent recurrent kernel ----------------
#define BM   128
#define BJ   16
#define BK   128
#define PA   272
#define PB   2064
#define SMB  0
#define SMA0 132096
#define SMA1 166912
#define SMTOT 201728
#define GSP  68

__global__ __launch_bounds__(256, 1) void lstm_persist()
{
    extern __shared__ __align__(16) char smem[];
    const uint32_t sb = smem_u32(smem);

    const int tid  = threadIdx.x;
    const int lane = tid & 31;
    const int warp = tid >> 5;
    const int wm   = warp >> 1;          // 0..3
    const int wn   = warp & 1;           // 0..1
    const int cta  = blockIdx.x;
    const int b0   = (cta >> 6) * BM;
    const int j0   = (cta & 63) * BJ;

    // resident w_hh slice: 64 rows x 2048B
#pragma unroll
    for (int l = 0; l < 32; l++) {
        int idx = l * 256 + tid;
        int r = idx >> 7;
        int q = idx & 127;
        int grow = ((r >> 4) << 10) + j0 + (r & 15);
        cpasync16(sb + SMB + r * PB + q * 16, g_whh + (size_t)grow * HID + q * 8);
    }
    CP_COMMIT();
    CP_WAIT(0);
    __syncthreads();

    const uint32_t laneoff  = (uint32_t)((lane & 15) * PA + (lane >> 4) * 16);
    const uint32_t laneoffB = (uint32_t)((lane & 15) * PB + (lane >> 4) * 16);

    for (int t = 0; t < TT; t++) {
        const __nv_bfloat16* hin = g_hb[t & 1];
        __nv_bfloat16* hout      = g_hb[(t + 1) & 1];

#pragma unroll
        for (int pc = 0; pc < 2; pc++) {
#pragma unroll
            for (int l = 0; l < 8; l++) {
                int idx = l * 256 + tid;
                int r = idx >> 4, q = idx & 15;
                cpasync16(sb + (pc ? SMA1 : SMA0) + r * PA + q * 16,
                          hin + (size_t)(b0 + r) * HID + pc * BK + q * 8);
            }
            CP_COMMIT();
        }

        float4 acc[2][4];
#pragma unroll
        for (int i = 0; i < 2; i++)
#pragma unroll
            for (int j = 0; j < 4; j++) acc[i][j] = make_float4(0.f, 0.f, 0.f, 0.f);

        for (int c = 0; c < 8; c++) {
            if (c < 7) CP_WAIT(1);
            else       CP_WAIT(0);
            __syncthreads();

            const uint32_t aB = sb + ((c & 1) ? SMA1 : SMA0);
            const uint32_t bB = sb + SMB + (uint32_t)(c * 256);

#pragma unroll
            for (int ks = 0; ks < 8; ks++) {
                uint32_t a[2][4];
#pragma unroll
                for (int mi = 0; mi < 2; mi++) {
                    uint32_t ad = aB + (uint32_t)((wm * 32 + mi * 16) * PA + ks * 32) + laneoff;
                    ldsm4(a[mi][0], a[mi][1], a[mi][2], a[mi][3], ad);
                }
#pragma unroll
                for (int nj = 0; nj < 2; nj++) {
                    uint32_t f0, f1, f2, f3;
                    uint32_t bd = bB + (uint32_t)((wn * 32 + nj * 16) * PB + ks * 32) + laneoffB;
                    ldsm4(f0, f1, f2, f3, bd);
#pragma unroll
                    for (int mi = 0; mi < 2; mi++) {
                        mma_bf16(acc[mi][nj * 2],     a[mi], f0, f2);
                        mma_bf16(acc[mi][nj * 2 + 1], a[mi], f1, f3);
                    }
                }
            }
            __syncthreads();
            if (c + 2 < 8) {
#pragma unroll
                for (int l = 0; l < 8; l++) {
                    int idx = l * 256 + tid;
                    int r = idx >> 4, q = idx & 15;
                    cpasync16(sb + ((c & 1) ? SMA1 : SMA0) + r * PA + q * 16,
                              hin + (size_t)(b0 + r) * HID + (c + 2) * BK + q * 8);
                }
                CP_COMMIT();
            }
        }

        // ---- stage gate tile (overlays A0) ----
        float* Gs = (float*)(smem + SMA0);
        const int gid = lane >> 2;
        const int tig = lane & 3;
#pragma unroll
        for (int mi = 0; mi < 2; mi++) {
#pragma unroll
            for (int q = 0; q < 4; q++) {
                int R = wm * 32 + mi * 16 + gid;
                int C = wn * 32 + (q >> 1) * 16 + (q & 1) * 8 + tig * 2;
                float4 v = acc[mi][q];
                Gs[R * GSP + C]           = v.x;
                Gs[R * GSP + C + 1]       = v.y;
                Gs[(R + 8) * GSP + C]     = v.z;
                Gs[(R + 8) * GSP + C + 1] = v.w;
            }
        }
        __syncthreads();

        // ---- fused LSTM cell update ----
#pragma unroll
        for (int l = 0; l < 8; l++) {
            int id = l * 256 + tid;
            int m  = id >> 4;
            int jj = id & 15;
            int bg = b0 + m;
            int jg = j0 + jj;
            size_t xb = ((size_t)t * BB + bg) * G4 + jg;

            float ig = Gs[m * GSP + jj]      + g_xg[xb];
            float fg = Gs[m * GSP + 16 + jj] + g_xg[xb + 1024];
            float gg = Gs[m * GSP + 32 + jj] + g_xg[xb + 2048];
            float og = Gs[m * GSP + 48 + jj] + g_xg[xb + 3072];

            float si = 1.f / (1.f + __expf(-ig));
            float sf = 1.f / (1.f + __expf(-fg));
            float so = 1.f / (1.f + __expf(-og));
            float tg = tanhf(gg);

            int hc = bg * HID + jg;
            float c2 = sf * g_c[hc] + si * tg;
            g_c[hc] = c2;
            hout[hc] = __float2bfloat16(so * tanhf(c2));
        }

        // ---- grid barrier (volatile-poll, single RMW per CTA) ----
        if (t + 1 < TT) {
            __threadfence();
            __syncthreads();
            if (tid == 0) {
                unsigned target = 128u * (unsigned)(t + 1);
                atomicAdd(&g_bar, 1u);
                volatile unsigned* vb = &g_bar;
                while (*vb < target) __nanosleep(32);
                __threadfence();
            }
            __syncthreads();
        }
    }
}

// ---------------- final FC + sigmoid (OUT = 1) ----------------
__global__ void final_fc(const float* __restrict__ fc_w,
                         const float* __restrict__ fc_b,
                         const __nv_bfloat16* __restrict__ h,
                         float* __restrict__ out)
{
    int bb = blockIdx.x;
    int tid = threadIdx.x;
    float s = 0.f;
    for (int k = tid; k < HID; k += 128)
        s += __bfloat162float(h[bb * HID + k]) * fc_w[k];
    __shared__ float red[128];
    red[tid] = s;
    __syncthreads();
    for (int off = 64; off > 0; off >>= 1) {
        if (tid < off) red[tid] += red[tid + off];
        __syncthreads();
    }
    if (tid == 0)
        out[bb] = 1.f / (1.f + expf(-(red[0] + fc_b[0])));
}

// ---------------- launch ----------------
extern "C" void kernel_launch(void* const* d_in, const int* in_sizes, int n_in,
                              void* d_out, int out_size)
{
    const void*  text = d_in[0];
    const float* emb  = (const float*)d_in[1];
    const float* w_ih = (const float*)d_in[2];
    const float* w_hh = (const float*)d_in[3];
    const float* b_ih = (const float*)d_in[4];
    const float* b_hh = (const float*)d_in[5];
    const float* fc_w = (const float*)d_in[6];
    const float* fc_b = (const float*)d_in[7];
    float* out = (float*)d_out;

    detect_dtype<<<1, 32>>>(text);
    zero_hc<<<(BB * HID + 255) / 256, 256>>>();

    __nv_bfloat16 *whh_b, *wih_b, *emb_b;
    cudaGetSymbolAddress((void**)&whh_b, g_whh);
    cudaGetSymbolAddress((void**)&wih_b, g_wih);
    cudaGetSymbolAddress((void**)&emb_b, g_emb);
    conv_f2b<<<((size_t)G4 * HID) / 1024, 256>>>(w_hh, whh_b);
    conv_f2b<<<((size_t)G4 * EMB) / 1024, 256>>>(w_ih, wih_b);
    conv_f2b<<<((size_t)VOCAB * EMB) / 1024, 256>>>(emb, emb_b);

    dim3 g1(512, 32);   // 128-token tiles x 128-gate tiles
    embed_mma<<<g1, 256>>>(text, b_ih, b_hh);

    cudaFuncSetAttribute(lstm_persist, cudaFuncAttributeMaxDynamicSharedMemorySize, SMTOT);
    lstm_persist<<<128, 256, SMTOT>>>();

    __nv_bfloat16* h0;
    cudaGetSymbolAddress((void**)&h0, g_hb);
    final_fc<<<BB, 128>>>(fc_w, fc_b, h0, out);
}

// round 8
// speedup vs baseline: 5.7170x; 1.2393x over previous
#include <cuda_runtime.h>
#include <cuda_bf16.h>
#include <math.h>
#include <stdint.h>

#define VOCAB 50000
#define EMB   512
#define HID   1024
#define G4    4096   // 4*HID
#define TT    256
#define BB    256

// ---------------- device scratch ----------------
__device__ float g_xg[(size_t)TT * BB * G4];          // [T][B][4H] input gates (+biases)
__device__ __nv_bfloat16 g_hb[2][BB * HID];           // double-buffered hidden (bf16)
__device__ __nv_bfloat16 g_whh[(size_t)G4 * HID];     // bf16 w_hh
__device__ __nv_bfloat16 g_wih[(size_t)G4 * EMB];     // bf16 w_ih
__device__ __nv_bfloat16 g_emb[(size_t)VOCAB * EMB];  // bf16 embedding table
__device__ int   g_is64;
__device__ unsigned g_bar2[2];                        // per-batch-group barriers

// ---------------- helpers ----------------
__device__ __forceinline__ uint32_t smem_u32(const void* p) {
    uint32_t a;
    asm("{ .reg .u64 t; cvta.to.shared.u64 t, %1; cvt.u32.u64 %0, t; }" : "=r"(a) : "l"(p));
    return a;
}
__device__ __forceinline__ void cpasync16(uint32_t dst, const void* src) {
    asm volatile("cp.async.cg.shared.global [%0], [%1], 16;" :: "r"(dst), "l"(src));
}
#define CP_COMMIT()  asm volatile("cp.async.commit_group;" ::: "memory")
#define CP_WAIT(n)   asm volatile("cp.async.wait_group %0;" :: "n"(n) : "memory")

__device__ __forceinline__ void ldsm4(uint32_t& r0, uint32_t& r1, uint32_t& r2, uint32_t& r3,
                                      uint32_t addr) {
    asm volatile("ldmatrix.sync.aligned.m8n8.x4.shared.b16 {%0,%1,%2,%3}, [%4];"
                 : "=r"(r0), "=r"(r1), "=r"(r2), "=r"(r3) : "r"(addr));
}
__device__ __forceinline__ void mma_bf16(float4& d, const uint32_t a[4],
                                         uint32_t b0, uint32_t b1) {
    asm volatile("mma.sync.aligned.m16n8k16.row.col.f32.bf16.bf16.f32 "
        "{%0,%1,%2,%3}, {%4,%5,%6,%7}, {%8,%9}, {%0,%1,%2,%3};"
        : "+f"(d.x), "+f"(d.y), "+f"(d.z), "+f"(d.w)
        : "r"(a[0]), "r"(a[1]), "r"(a[2]), "r"(a[3]), "r"(b0), "r"(b1));
}

__device__ __forceinline__ float sigmoid_fast(float x) {
    return 1.f / (1.f + __expf(-x));
}
__device__ __forceinline__ float tanh_fast(float x) {
    x = fminf(fmaxf(x, -15.f), 15.f);
    float e = __expf(2.f * x);
    return (e - 1.f) / (e + 1.f);
}

// ---------------- prep kernels ----------------
__global__ void detect_dtype(const void* text) {
    if (threadIdx.x == 0 && blockIdx.x == 0) {
        const long long* p = (const long long*)text;
        int ok = 1;
        for (int i = 0; i < 64; i++) {
            long long v = p[i];
            if (v < 0 || v >= VOCAB) ok = 0;
        }
        g_is64 = ok;
    }
}

__global__ void zero_hc() {
    int i = blockIdx.x * blockDim.x + threadIdx.x;
    if (i < 2) g_bar2[i] = 0u;
    if (i < BB * HID) {
        g_hb[0][i] = __float2bfloat16(0.f);
        g_hb[1][i] = __float2bfloat16(0.f);
    }
}

__global__ void conv_f2b(const float* __restrict__ src, __nv_bfloat16* __restrict__ dst) {
    size_t i = ((size_t)blockIdx.x * 256 + threadIdx.x) * 4;
    float4 v = *(const float4*)(src + i);
    *(__nv_bfloat162*)(dst + i)     = __floats2bfloat162_rn(v.x, v.y);
    *(__nv_bfloat162*)(dst + i + 2) = __floats2bfloat162_rn(v.z, v.w);
}

// ---------------- bf16 MMA embedding gather + input GEMM ----------------
#define EPITCH 80
#define ESA0   0
#define ESA1   10240
#define ESB0   20480
#define ESB1   30720
#define ESEND  40960

__global__ __launch_bounds__(256) void embed_mma(
    const void* __restrict__ text,
    const float* __restrict__ b_ih,
    const float* __restrict__ b_hh)
{
    __shared__ __align__(16) char smem[ESEND];
    __shared__ int   toks[128];
    __shared__ float bias[128];
    const uint32_t sb = smem_u32(smem);

    const int tid  = threadIdx.x;
    const int lane = tid & 31;
    const int warp = tid >> 5;
    const int wm   = warp >> 1;
    const int wn   = warp & 1;
    const int m0 = blockIdx.x * 128;
    const int n0 = blockIdx.y * 128;

    if (tid < 128) {
        int m = m0 + tid;
        toks[tid] = g_is64 ? (int)((const long long*)text)[m]
                           : ((const int*)text)[m];
        bias[tid] = b_ih[n0 + tid] + b_hh[n0 + tid];
    }
    __syncthreads();

    auto issue = [&](int buf, int chunk) {
        const int k0 = chunk * 32;
#pragma unroll
        for (int l = 0; l < 2; l++) {
            int idx = l * 256 + tid;
            int r = idx >> 2, q = (idx & 3) << 3;
            cpasync16(sb + (buf ? ESA1 : ESA0) + r * EPITCH + q * 2,
                      g_emb + (size_t)toks[r] * EMB + k0 + q);
        }
#pragma unroll
        for (int l = 0; l < 2; l++) {
            int idx = l * 256 + tid;
            int r = idx >> 2, q = (idx & 3) << 3;
            cpasync16(sb + (buf ? ESB1 : ESB0) + r * EPITCH + q * 2,
                      g_wih + (size_t)(n0 + r) * EMB + k0 + q);
        }
        CP_COMMIT();
    };

    float4 acc[2][8];
#pragma unroll
    for (int i = 0; i < 2; i++)
#pragma unroll
        for (int j = 0; j < 8; j++) acc[i][j] = make_float4(0.f, 0.f, 0.f, 0.f);

    issue(0, 0);
    issue(1, 1);

    const uint32_t laneoff = (uint32_t)((lane & 15) * EPITCH + (lane >> 4) * 16);

    for (int c = 0; c < 16; c++) {
        if (c < 15) CP_WAIT(1);
        else        CP_WAIT(0);
        __syncthreads();

        const uint32_t aB = sb + ((c & 1) ? ESA1 : ESA0);
        const uint32_t bB = sb + ((c & 1) ? ESB1 : ESB0);

#pragma unroll
        for (int ks = 0; ks < 2; ks++) {
            uint32_t a[2][4];
#pragma unroll
            for (int mi = 0; mi < 2; mi++) {
                uint32_t ad = aB + (uint32_t)((wm * 32 + mi * 16) * EPITCH + ks * 32) + laneoff;
                ldsm4(a[mi][0], a[mi][1], a[mi][2], a[mi][3], ad);
            }
#pragma unroll
            for (int nj = 0; nj < 4; nj++) {
                uint32_t f0, f1, f2, f3;
                uint32_t bd = bB + (uint32_t)((wn * 64 + nj * 16) * EPITCH + ks * 32) + laneoff;
                ldsm4(f0, f1, f2, f3, bd);
#pragma unroll
                for (int mi = 0; mi < 2; mi++) {
                    mma_bf16(acc[mi][nj * 2],     a[mi], f0, f2);
                    mma_bf16(acc[mi][nj * 2 + 1], a[mi], f1, f3);
                }
            }
        }
        __syncthreads();
        if (c + 2 < 16) issue(c & 1, c + 2);
    }

    const int gid = lane >> 2;
    const int tig = lane & 3;
#pragma unroll
    for (int mi = 0; mi < 2; mi++) {
        int R = wm * 32 + mi * 16 + gid;
        int mA = m0 + R;
        int mB = mA + 8;
        size_t baseA = ((size_t)(mA & 255) * BB + (mA >> 8)) * G4 + n0;
        size_t baseB = ((size_t)(mB & 255) * BB + (mB >> 8)) * G4 + n0;
#pragma unroll
        for (int nj = 0; nj < 4; nj++) {
#pragma unroll
            for (int h = 0; h < 2; h++) {
                float4 v = acc[mi][nj * 2 + h];
                int C = wn * 64 + nj * 16 + h * 8 + tig * 2;
                g_xg[baseA + C]     = v.x + bias[C];
                g_xg[baseA + C + 1] = v.y + bias[C + 1];
                g_xg[baseB + C]     = v.z + bias[C];
                g_xg[baseB + C + 1] = v.w + bias[C + 1];
            }
        }
    }
}

// ---------------- persistent recurrent kernel ----------------
#define BM   128
#define BJ   16
#define BK   128
#define PA   272
#define PB   2064
#define SMB  0
#define SMA0 132096
#define SMA1 166912
#define SMTOT 201728
#define GSP  68

__global__ __launch_bounds__(256, 1) void lstm_persist()
{
    extern __shared__ __align__(16) char smem[];
    const uint32_t sb = smem_u32(smem);

    const int tid  = threadIdx.x;
    const int lane = tid & 31;
    const int warp = tid >> 5;
    const int wm   = warp >> 1;
    const int wn   = warp & 1;
    const int cta  = blockIdx.x;
    const int grp  = cta >> 6;           // batch group 0/1 (independent recurrences)
    const int b0   = grp * BM;
    const int j0   = (cta & 63) * BJ;

    // resident w_hh slice: 64 rows x 2048B
#pragma unroll
    for (int l = 0; l < 32; l++) {
        int idx = l * 256 + tid;
        int r = idx >> 7;
        int q = idx & 127;
        int grow = ((r >> 4) << 10) + j0 + (r & 15);
        cpasync16(sb + SMB + r * PB + q * 16, g_whh + (size_t)grow * HID + q * 8);
    }
    CP_COMMIT();
    CP_WAIT(0);
    __syncthreads();

    const uint32_t laneoff  = (uint32_t)((lane & 15) * PA + (lane >> 4) * 16);
    const uint32_t laneoffB = (uint32_t)((lane & 15) * PB + (lane >> 4) * 16);

    // per-thread persistent cell state + xg prefetch registers
    const int mrow = tid >> 4;           // 0..15 base row offset
    const int jj   = tid & 15;
    float cr[8];
#pragma unroll
    for (int l = 0; l < 8; l++) cr[l] = 0.f;
    float xr[8][4];

    // prefetch xg for step t into registers (independent of h / barrier)
    auto pre_xg = [&](int t) {
        const float* xb = g_xg + ((size_t)t * BB + b0) * G4 + j0 + jj;
#pragma unroll
        for (int l = 0; l < 8; l++) {
            const float* p = xb + (size_t)(l * 16 + mrow) * G4;
            xr[l][0] = p[0];
            xr[l][1] = p[1024];
            xr[l][2] = p[2048];
            xr[l][3] = p[3072];
        }
    };
    pre_xg(0);

    unsigned* bp = &g_bar2[grp];

    for (int t = 0; t < TT; t++) {
        const __nv_bfloat16* hin = g_hb[t & 1];
        __nv_bfloat16* hout      = g_hb[(t + 1) & 1];

#pragma unroll
        for (int pc = 0; pc < 2; pc++) {
#pragma unroll
            for (int l = 0; l < 8; l++) {
                int idx = l * 256 + tid;
                int r = idx >> 4, q = idx & 15;
                cpasync16(sb + (pc ? SMA1 : SMA0) + r * PA + q * 16,
                          hin + (size_t)(b0 + r) * HID + pc * BK + q * 8);
            }
            CP_COMMIT();
        }

        float4 acc[2][4];
#pragma unroll
        for (int i = 0; i < 2; i++)
#pragma unroll
            for (int j = 0; j < 4; j++) acc[i][j] = make_float4(0.f, 0.f, 0.f, 0.f);

        for (int c = 0; c < 8; c++) {
            if (c < 7) CP_WAIT(1);
            else       CP_WAIT(0);
            __syncthreads();

            const uint32_t aB = sb + ((c & 1) ? SMA1 : SMA0);
            const uint32_t bB = sb + SMB + (uint32_t)(c * 256);

#pragma unroll
            for (int ks = 0; ks < 8; ks++) {
                uint32_t a[2][4];
#pragma unroll
                for (int mi = 0; mi < 2; mi++) {
                    uint32_t ad = aB + (uint32_t)((wm * 32 + mi * 16) * PA + ks * 32) + laneoff;
                    ldsm4(a[mi][0], a[mi][1], a[mi][2], a[mi][3], ad);
                }
#pragma unroll
                for (int nj = 0; nj < 2; nj++) {
                    uint32_t f0, f1, f2, f3;
                    uint32_t bd = bB + (uint32_t)((wn * 32 + nj * 16) * PB + ks * 32) + laneoffB;
                    ldsm4(f0, f1, f2, f3, bd);
#pragma unroll
                    for (int mi = 0; mi < 2; mi++) {
                        mma_bf16(acc[mi][nj * 2],     a[mi], f0, f2);
                        mma_bf16(acc[mi][nj * 2 + 1], a[mi], f1, f3);
                    }
                }
            }
            __syncthreads();
            if (c + 2 < 8) {
#pragma unroll
                for (int l = 0; l < 8; l++) {
                    int idx = l * 256 + tid;
                    int r = idx >> 4, q = idx & 15;
                    cpasync16(sb + ((c & 1) ? SMA1 : SMA0) + r * PA + q * 16,
                              hin + (size_t)(b0 + r) * HID + (c + 2) * BK + q * 8);
                }
                CP_COMMIT();
            }
        }

        // ---- stage gate tile (overlays A0) ----
        float* Gs = (float*)(smem + SMA0);
        const int gid = lane >> 2;
        const int tig = lane & 3;
#pragma unroll
        for (int mi = 0; mi < 2; mi++) {
#pragma unroll
            for (int q = 0; q < 4; q++) {
                int R = wm * 32 + mi * 16 + gid;
                int C = wn * 32 + (q >> 1) * 16 + (q & 1) * 8 + tig * 2;
                float4 v = acc[mi][q];
                Gs[R * GSP + C]           = v.x;
                Gs[R * GSP + C + 1]       = v.y;
                Gs[(R + 8) * GSP + C]     = v.z;
                Gs[(R + 8) * GSP + C + 1] = v.w;
            }
        }
        __syncthreads();

        // ---- fused LSTM cell update (c lives in registers) ----
#pragma unroll
        for (int l = 0; l < 8; l++) {
            int m = l * 16 + mrow;
            float ig = Gs[m * GSP + jj]      + xr[l][0];
            float fg = Gs[m * GSP + 16 + jj] + xr[l][1];
            float gg = Gs[m * GSP + 32 + jj] + xr[l][2];
            float og = Gs[m * GSP + 48 + jj] + xr[l][3];

            float si = sigmoid_fast(ig);
            float sf = sigmoid_fast(fg);
            float so = sigmoid_fast(og);
            float tg = tanh_fast(gg);

            float c2 = sf * cr[l] + si * tg;
            cr[l] = c2;
            hout[(b0 + m) * HID + j0 + jj] = __float2bfloat16(so * tanh_fast(c2));
        }

        if (t + 1 < TT) {
            pre_xg(t + 1);   // overlaps with barrier spin (xg independent of h)
            __syncthreads();
            if (tid == 0) {
                asm volatile("red.release.gpu.global.add.u32 [%0], 1;"
                             :: "l"(bp) : "memory");
                unsigned target = 64u * (unsigned)(t + 1);
                unsigned v;
                do {
                    asm volatile("ld.acquire.gpu.global.u32 %0, [%1];"
                                 : "=r"(v) : "l"(bp) : "memory");
                    if (v >= target) break;
                    __nanosleep(32);
                } while (1);
            }
            __syncthreads();
        }
    }
}

// ---------------- final FC + sigmoid (OUT = 1) ----------------
__global__ void final_fc(const float* __restrict__ fc_w,
                         const float* __restrict__ fc_b,
                         const __nv_bfloat16* __restrict__ h,
                         float* __restrict__ out)
{
    int bb = blockIdx.x;
    int tid = threadIdx.x;
    float s = 0.f;
    for (int k = tid; k < HID; k += 128)
        s += __bfloat162float(h[bb * HID + k]) * fc_w[k];
    __shared__ float red[128];
    red[tid] = s;
    __syncthreads();
    for (int off = 64; off > 0; off >>= 1) {
        if (tid < off) red[tid] += red[tid + off];
        __syncthreads();
    }
    if (tid == 0)
        out[bb] = 1.f / (1.f + expf(-(red[0] + fc_b[0])));
}

// ---------------- launch ----------------
extern "C" void kernel_launch(void* const* d_in, const int* in_sizes, int n_in,
                              void* d_out, int out_size)
{
    const void*  text = d_in[0];
    const float* emb  = (const float*)d_in[1];
    const float* w_ih = (const float*)d_in[2];
    const float* w_hh = (const float*)d_in[3];
    const float* b_ih = (const float*)d_in[4];
    const float* b_hh = (const float*)d_in[5];
    const float* fc_w = (const float*)d_in[6];
    const float* fc_b = (const float*)d_in[7];
    float* out = (float*)d_out;

    detect_dtype<<<1, 32>>>(text);
    zero_hc<<<(BB * HID + 255) / 256, 256>>>();

    __nv_bfloat16 *whh_b, *wih_b, *emb_b;
    cudaGetSymbolAddress((void**)&whh_b, g_whh);
    cudaGetSymbolAddress((void**)&wih_b, g_wih);
    cudaGetSymbolAddress((void**)&emb_b, g_emb);
    conv_f2b<<<((size_t)G4 * HID) / 1024, 256>>>(w_hh, whh_b);
    conv_f2b<<<((size_t)G4 * EMB) / 1024, 256>>>(w_ih, wih_b);
    conv_f2b<<<((size_t)VOCAB * EMB) / 1024, 256>>>(emb, emb_b);

    dim3 g1(512, 32);
    embed_mma<<<g1, 256>>>(text, b_ih, b_hh);

    cudaFuncSetAttribute(lstm_persist, cudaFuncAttributeMaxDynamicSharedMemorySize, SMTOT);
    lstm_persist<<<128, 256, SMTOT>>>();

    __nv_bfloat16* h0;
    cudaGetSymbolAddress((void**)&h0, g_hb);
    final_fc<<<BB, 128>>>(fc_w, fc_b, h0, out);
}